// round 7
// baseline (speedup 1.0000x reference)
#include <cuda_runtime.h>
#include <cstdint>

// AddRadiusEdgeIndex: pairwise squared distances + radius mask, N=8192, r=1.
// Output: [N*N] masked_dist2 (f32), then [N*N] edge_mask as 0.0/1.0 (f32).
//
// Numerics replicate the reference bit-exactly:
//   sq[i]  = x*x + y*y + z*z                (plain mul/add, no FMA contraction)
//   dot    = fma(z, z', fma(y, y', x*x))    (FMA chain, gemm-like)
//   d2     = (sq_i + sq_j) - 2*dot ;  d2 = max(d2, 0) ; mask = d2 <= 1
//
// Store-path-bound (chip LTS cap ~6.4 TB/s measured, invariant across 5 kernel
// shapes). This variant splits the two output streams into two sequential
// kernels so each is a single pure linear write stream (compute is ~15% of
// pipe, so recomputing it in the mask pass is free).

#define TI 32
#define TJ 256
#define R2 1.0f

__device__ __forceinline__ void stg256_cs(float* p,
                                          float v0, float v1, float v2, float v3,
                                          float v4, float v5, float v6, float v7)
{
    asm volatile("st.global.cs.v8.f32 [%0], {%1,%2,%3,%4,%5,%6,%7,%8};"
                 :: "l"(p), "f"(v0), "f"(v1), "f"(v2), "f"(v3),
                    "f"(v4), "f"(v5), "f"(v6), "f"(v7)
                 : "memory");
}

// MODE 0: write masked_dist2.  MODE 1: write mask (0/1).
template <int MODE>
__global__ __launch_bounds__(256, 6)
void radius_edge_kernel(const float* __restrict__ pos,
                        float* __restrict__ out,
                        int n)
{
    __shared__ float jx[TJ], jy[TJ], jz[TJ], jsq[TJ];
    __shared__ float ix[TI], iy[TI], iz[TI], isq[TI];

    const int j0 = blockIdx.x * TJ;
    const int i0 = blockIdx.y * TI;
    const int t  = threadIdx.x;   // 256 threads

    // Stage tiles. sq uses plain mul/add rounding (matches jnp.sum(pos*pos)).
    {
        int j = j0 + t;           // t covers all TJ=256
        float x = pos[3 * j + 0];
        float y = pos[3 * j + 1];
        float z = pos[3 * j + 2];
        jx[t] = x; jy[t] = y; jz[t] = z;
        jsq[t] = __fadd_rn(__fadd_rn(__fmul_rn(x, x), __fmul_rn(y, y)),
                           __fmul_rn(z, z));
    }
    if (t < TI) {
        int i = i0 + t;
        float x = pos[3 * i + 0];
        float y = pos[3 * i + 1];
        float z = pos[3 * i + 2];
        ix[t] = x; iy[t] = y; iz[t] = z;
        isq[t] = __fadd_rn(__fadd_rn(__fmul_rn(x, x), __fmul_rn(y, y)),
                           __fmul_rn(z, z));
    }
    __syncthreads();

    // Thread layout: tx in [0,32) -> 8 consecutive j, ty in [0,8) -> i stride.
    const int tx = t & 31;
    const int ty = t >> 5;
    const int jj = tx * 8;

    float xj[8], yj[8], zj[8], sj[8];
#pragma unroll
    for (int q = 0; q < 8; ++q) {
        xj[q] = jx[jj + q];
        yj[q] = jy[jj + q];
        zj[q] = jz[jj + q];
        sj[q] = jsq[jj + q];
    }

    const size_t base = (size_t)(i0 + ty) * (size_t)n + (size_t)(j0 + jj);
    float* __restrict__ optr = out + base;
    const size_t rowstep = (size_t)n * 8;     // 8 rows, in floats

#pragma unroll
    for (int k = 0; k < TI / 8; ++k) {
        const int il = ty + k * 8;            // local i (0..31)
        const float xi = ix[il], yi = iy[il], zi = iz[il], si = isq[il];

        float v[8];
#pragma unroll
        for (int q = 0; q < 8; ++q) {
            float dt = __fmaf_rn(zi, zj[q], __fmaf_rn(yi, yj[q], __fmul_rn(xi, xj[q])));
            float dd = __fsub_rn(__fadd_rn(si, sj[q]), __fadd_rn(dt, dt));
            dd = fmaxf(dd, 0.0f);
            const bool in_r = (dd <= R2);
            if (MODE == 0) {
                v[q] = in_r ? dd : 0.0f;      // masked_dist2
            } else {
                v[q] = in_r ? 1.0f : 0.0f;    // edge_mask as float
            }
        }

        stg256_cs(optr, v[0], v[1], v[2], v[3], v[4], v[5], v[6], v[7]);
        optr += rowstep;
    }
}

extern "C" void kernel_launch(void* const* d_in, const int* in_sizes, int n_in,
                              void* d_out, int out_size)
{
    const float* pos = (const float*)d_in[0];
    const int n = in_sizes[0] / 3;           // 8192

    float* out  = (float*)d_out;
    float* dist = out;
    const long long nn = (long long)n * (long long)n;
    float* mask = ((long long)out_size >= 2 * nn) ? (out + (size_t)nn) : nullptr;

    dim3 grid((n + TJ - 1) / TJ, (n + TI - 1) / TI);
    radius_edge_kernel<0><<<grid, 256>>>(pos, dist, n);
    if (mask != nullptr) {
        radius_edge_kernel<1><<<grid, 256>>>(pos, mask, n);
    }
}

// round 8
// speedup vs baseline: 1.7141x; 1.7141x over previous
#include <cuda_runtime.h>
#include <cstdint>

// AddRadiusEdgeIndex: pairwise squared distances + radius mask, N=8192, r=1.
// Output: [N*N] masked_dist2 (f32), then [N*N] edge_mask as 0.0/1.0 (f32).
//
// Numerics deliberately replicate the reference bit-exactly (rel_err = 0.0):
//   sq[i]  = x*x + y*y + z*z                (plain mul/add, no FMA contraction)
//   dot    = fma(z, z', fma(y, y', x*x))    (FMA chain, gemm-like)
//   d2     = (sq_i + sq_j) - 2*dot ;  d2 = max(d2, 0) ; mask = d2 <= 1
//
// FINAL FORM — measured at the DRAM write-stream ceiling:
//   512 MB written / 75.8 us = 6.75 TB/s app bandwidth, DRAM busy ~81%.
//   Invariant (+-0.1%) across: tile shapes 64x128/32x256/16x512, eviction
//   policy, occupancy 34%<->68%, STG.128 vs STG.256, persistent grid
//   (regressed), split single-stream kernels (regressed: one stream only
//   drives 4.5 TB/s — the dist+mask store pair per iteration is required
//   parallelism). Dual-stream, 32x256 tile, 256-bit evict-streaming stores.

#define TI 32
#define TJ 256
#define R2 1.0f

__device__ __forceinline__ void stg256_cs(float* p,
                                          float v0, float v1, float v2, float v3,
                                          float v4, float v5, float v6, float v7)
{
    asm volatile("st.global.cs.v8.f32 [%0], {%1,%2,%3,%4,%5,%6,%7,%8};"
                 :: "l"(p), "f"(v0), "f"(v1), "f"(v2), "f"(v3),
                    "f"(v4), "f"(v5), "f"(v6), "f"(v7)
                 : "memory");
}

__global__ __launch_bounds__(256, 3)
void radius_edge_kernel(const float* __restrict__ pos,
                        float* __restrict__ dist_out,
                        float* __restrict__ mask_out,
                        int n)
{
    __shared__ float jx[TJ], jy[TJ], jz[TJ], jsq[TJ];
    __shared__ float ix[TI], iy[TI], iz[TI], isq[TI];

    const int j0 = blockIdx.x * TJ;
    const int i0 = blockIdx.y * TI;
    const int t  = threadIdx.x;   // 256 threads

    // Stage tiles. sq uses plain mul/add rounding (matches jnp.sum(pos*pos)).
    {
        int j = j0 + t;           // t covers all TJ=256
        float x = pos[3 * j + 0];
        float y = pos[3 * j + 1];
        float z = pos[3 * j + 2];
        jx[t] = x; jy[t] = y; jz[t] = z;
        jsq[t] = __fadd_rn(__fadd_rn(__fmul_rn(x, x), __fmul_rn(y, y)),
                           __fmul_rn(z, z));
    }
    if (t < TI) {
        int i = i0 + t;
        float x = pos[3 * i + 0];
        float y = pos[3 * i + 1];
        float z = pos[3 * i + 2];
        ix[t] = x; iy[t] = y; iz[t] = z;
        isq[t] = __fadd_rn(__fadd_rn(__fmul_rn(x, x), __fmul_rn(y, y)),
                           __fmul_rn(z, z));
    }
    __syncthreads();

    // Thread layout: tx in [0,32) -> 8 consecutive j, ty in [0,8) -> i stride.
    const int tx = t & 31;
    const int ty = t >> 5;
    const int jj = tx * 8;

    // Pull the j-octet into registers once.
    float xj[8], yj[8], zj[8], sj[8];
#pragma unroll
    for (int q = 0; q < 8; ++q) {
        xj[q] = jx[jj + q];
        yj[q] = jy[jj + q];
        zj[q] = jz[jj + q];
        sj[q] = jsq[jj + q];
    }

    // Row pointers: start at row (i0+ty), advance 8 rows per iteration.
    const size_t base = (size_t)(i0 + ty) * (size_t)n + (size_t)(j0 + jj);
    float* __restrict__ dptr = dist_out + base;
    float* __restrict__ mptr = mask_out ? mask_out + base : nullptr;
    const size_t rowstep = (size_t)n * 8;     // 8 rows, in floats

#pragma unroll
    for (int k = 0; k < TI / 8; ++k) {
        const int il = ty + k * 8;            // local i (0..31)
        const float xi = ix[il], yi = iy[il], zi = iz[il], si = isq[il];

        float d[8], m[8];
#pragma unroll
        for (int q = 0; q < 8; ++q) {
            float dt = __fmaf_rn(zi, zj[q], __fmaf_rn(yi, yj[q], __fmul_rn(xi, xj[q])));
            float dd = __fsub_rn(__fadd_rn(si, sj[q]), __fadd_rn(dt, dt));
            dd = fmaxf(dd, 0.0f);
            m[q] = (dd <= R2) ? 1.0f : 0.0f;
            d[q] = (m[q] != 0.0f) ? dd : 0.0f;
        }

        stg256_cs(dptr, d[0], d[1], d[2], d[3], d[4], d[5], d[6], d[7]);
        dptr += rowstep;
        if (mptr) {
            stg256_cs(mptr, m[0], m[1], m[2], m[3], m[4], m[5], m[6], m[7]);
            mptr += rowstep;
        }
    }
}

extern "C" void kernel_launch(void* const* d_in, const int* in_sizes, int n_in,
                              void* d_out, int out_size)
{
    const float* pos = (const float*)d_in[0];
    const int n = in_sizes[0] / 3;           // 8192

    float* out  = (float*)d_out;
    float* dist = out;
    const long long nn = (long long)n * (long long)n;
    float* mask = ((long long)out_size >= 2 * nn) ? (out + (size_t)nn) : nullptr;

    dim3 grid((n + TJ - 1) / TJ, (n + TI - 1) / TI);
    radius_edge_kernel<<<grid, 256>>>(pos, dist, mask, n);
}